// round 1
// baseline (speedup 1.0000x reference)
#include <cuda_runtime.h>
#include <cstddef>

// Problem constants
namespace {
constexpr int Bsz = 512;
constexpr int Tsz = 1024;
constexpr int INs = 3;
constexpr int Hs  = 64;
constexpr int Gs  = 192;   // 3*H
}

// Scratch (device globals — no allocation in kernel_launch allowed)
__device__ float g_h1 [(size_t)Bsz * Tsz * Hs];   // layer-0 output, (B*T, 64)
__device__ float g_gx1[(size_t)Bsz * Tsz * Gs];   // layer-1 input projection, (B*T, 192)

__device__ __forceinline__ float sigmoidf_(float v) {
    return 1.0f / (1.0f + __expf(-v));
}

// ---------------------------------------------------------------------------
// GRU scan kernel (one layer). Grid: 128 CTAs, each owns 4 batch rows.
// blockDim = 768: thread = (row_local = tx/192, gate g = tx%192).
// W_hh column for gate g lives in 64 registers. Hidden state in shared,
// read as float4 broadcasts. Two __syncthreads per timestep.
// LAYER==0: gx computed inline from x (IN=3), output -> g_h1.
// LAYER==1: gx read from g_gx1 (precomputed GEMM), output -> d_out (+ final h).
// ---------------------------------------------------------------------------
template <int LAYER>
__global__ void __launch_bounds__(768, 1) gru_scan_kernel(
    const float* __restrict__ Whh,     // (192,64) row-major
    const float* __restrict__ bhh_p,   // (192)
    const float* __restrict__ Wih,     // (192,3)  layer0 only
    const float* __restrict__ bih_p,   // (192)    layer0 only
    const float* __restrict__ x,       // (B,T,3)  layer0 only
    float* __restrict__ seq_out,       // (B,T,64) layer1 only
    float* __restrict__ final_out)     // (B,64)   layer1 only
{
    __shared__ float sh_h [4][64];
    __shared__ float sh_xa[4][192];
    __shared__ float sh_ha[4][192];

    const int tx = threadIdx.x;
    const int g  = tx % Gs;        // gate index 0..191
    const int rl = tx / Gs;        // row within CTA 0..3

    // Recurrent weight column in registers (fully unrolled use keeps it there)
    float w[64];
#pragma unroll
    for (int k = 0; k < 64; k++) w[k] = Whh[g * 64 + k];
    const float bh = bhh_p[g];

    float wi0 = 0.f, wi1 = 0.f, wi2 = 0.f, bi = 0.f;
    if (LAYER == 0) {
        wi0 = Wih[g * 3 + 0];
        wi1 = Wih[g * 3 + 1];
        wi2 = Wih[g * 3 + 2];
        bi  = bih_p[g];
    }

    // h0 = 0
    if (tx < 256) sh_h[tx >> 6][tx & 63] = 0.0f;
    __syncthreads();

    const int rg = blockIdx.x * 4 + rl;   // global batch row for compute phase
    const float* __restrict__ xrow  = (LAYER == 0) ? (x + (size_t)rg * Tsz * INs) : nullptr;
    const float* __restrict__ gxrow = (LAYER == 1) ? (&g_gx1[(size_t)rg * Tsz * Gs]) : nullptr;
    float* __restrict__ orow = (LAYER == 0) ? (&g_h1[0]) : seq_out;

    const float4* __restrict__ sh_h4 = reinterpret_cast<const float4*>(&sh_h[rl][0]);

    for (int t = 0; t < Tsz; t++) {
        // ----- input-projection part (latency hidden under the FMA loop) -----
        float xa;
        if (LAYER == 0) {
            float x0 = xrow[t * 3 + 0];
            float x1 = xrow[t * 3 + 1];
            float x2 = xrow[t * 3 + 2];
            xa = fmaf(x2, wi2, fmaf(x1, wi1, fmaf(x0, wi0, bi)));
        } else {
            xa = __ldg(&gxrow[(size_t)t * Gs + g]);
        }

        // ----- recurrent dot: gh[g] = b_hh[g] + sum_k h[k] * W_hh[g][k] -----
        float ha = bh;
#pragma unroll
        for (int k4 = 0; k4 < 16; k4++) {
            float4 h4 = sh_h4[k4];                 // broadcast LDS.128
            ha = fmaf(h4.x, w[4 * k4 + 0], ha);
            ha = fmaf(h4.y, w[4 * k4 + 1], ha);
            ha = fmaf(h4.z, w[4 * k4 + 2], ha);
            ha = fmaf(h4.w, w[4 * k4 + 3], ha);
        }

        sh_xa[rl][g] = xa;
        sh_ha[rl][g] = ha;
        __syncthreads();

        // ----- gate combine + state update (256 threads = 4 rows x 64) -----
        if (tx < 256) {
            const int r2 = tx >> 6, j = tx & 63;
            float ar = sh_xa[r2][j]      + sh_ha[r2][j];
            float az = sh_xa[r2][j + 64] + sh_ha[r2][j + 64];
            float rr = sigmoidf_(ar);
            float zz = sigmoidf_(az);
            float nn = tanhf(fmaf(rr, sh_ha[r2][j + 128], sh_xa[r2][j + 128]));
            float hp = sh_h[r2][j];
            float hn = fmaf(zz, hp - nn, nn);      // (1-z)*n + z*h
            sh_h[r2][j] = hn;                       // safe: all reads done pre-barrier
            const int rowg = blockIdx.x * 4 + r2;
            orow[((size_t)rowg * Tsz + t) * Hs + j] = hn;
            if (LAYER == 1 && t == Tsz - 1) {
                final_out[rowg * Hs + j] = hn;
            }
        }
        __syncthreads();
    }
}

// ---------------------------------------------------------------------------
// gx1 = h1 @ W_ih1^T + b_ih1   (M = B*T = 524288, N = 192, K = 64)
// Fully parallel. Thread = (row-group 0/1, gate). W_ih1 column in registers,
// h1 row loaded via uniform LDG.128 broadcasts (L1-served after first warp).
// Grid 256 CTAs x 2048 rows each, blockDim 384 (2 rows in flight).
// ---------------------------------------------------------------------------
__global__ void __launch_bounds__(384, 2) gx1_gemm_kernel(
    const float* __restrict__ Wih,   // (192,64)
    const float* __restrict__ bih)   // (192)
{
    const int tx   = threadIdx.x;
    const int g    = tx % Gs;
    const int rgrp = tx / Gs;        // 0 or 1

    float w[64];
#pragma unroll
    for (int k = 0; k < 64; k++) w[k] = Wih[g * 64 + k];
    const float bi = bih[g];

    const int base = blockIdx.x * 2048;
    for (int it = 0; it < 1024; it++) {
        const int row = base + it * 2 + rgrp;
        const float4* __restrict__ hr =
            reinterpret_cast<const float4*>(&g_h1[(size_t)row * Hs]);
        float acc = bi;
#pragma unroll
        for (int k4 = 0; k4 < 16; k4++) {
            float4 h4 = __ldg(&hr[k4]);
            acc = fmaf(h4.x, w[4 * k4 + 0], acc);
            acc = fmaf(h4.y, w[4 * k4 + 1], acc);
            acc = fmaf(h4.z, w[4 * k4 + 2], acc);
            acc = fmaf(h4.w, w[4 * k4 + 3], acc);
        }
        g_gx1[(size_t)row * Gs + g] = acc;   // coalesced (lanes = consecutive g)
    }
}

// ---------------------------------------------------------------------------
// Launch: layer0 scan -> gx1 GEMM -> layer1 scan (stream-ordered).
// ---------------------------------------------------------------------------
extern "C" void kernel_launch(void* const* d_in, const int* in_sizes, int n_in,
                              void* d_out, int out_size)
{
    (void)in_sizes; (void)n_in; (void)out_size;
    const float* x     = (const float*)d_in[0];
    const float* W_ih0 = (const float*)d_in[1];
    const float* W_hh0 = (const float*)d_in[2];
    const float* b_ih0 = (const float*)d_in[3];
    const float* b_hh0 = (const float*)d_in[4];
    const float* W_ih1 = (const float*)d_in[5];
    const float* W_hh1 = (const float*)d_in[6];
    const float* b_ih1 = (const float*)d_in[7];
    const float* b_hh1 = (const float*)d_in[8];

    float* out    = (float*)d_out;
    float* finalh = out + (size_t)Bsz * Tsz * Hs;

    gru_scan_kernel<0><<<Bsz / 4, 768>>>(W_hh0, b_hh0, W_ih0, b_ih0, x,
                                         nullptr, nullptr);
    gx1_gemm_kernel<<<256, 384>>>(W_ih1, b_ih1);
    gru_scan_kernel<1><<<Bsz / 4, 768>>>(W_hh1, b_hh1, nullptr, nullptr, nullptr,
                                         out, finalh);
}

// round 2
// speedup vs baseline: 1.4940x; 1.4940x over previous
#include <cuda_runtime.h>
#include <cstdint>
#include <cstddef>

namespace {
constexpr int Bsz = 512, Tsz = 1024, Hs = 64, Gs = 192;
constexpr size_t MROWS = (size_t)Bsz * Tsz;   // 524288
}

// Scratch (device globals — allocation is forbidden in kernel_launch)
__device__ float g_h1[MROWS * Hs];   // layer-0 hidden sequence  (134 MB)
__device__ float g_gx[MROWS * Gs];   // gx buffer, reused by both layers (402 MB)

using ull = unsigned long long;

__device__ __forceinline__ void unpack2(ull v, float& lo, float& hi) {
    asm("mov.b64 {%0,%1},%2;" : "=f"(lo), "=f"(hi) : "l"(v));
}
__device__ __forceinline__ ull ffma2(ull a, ull b, ull c) {
    ull d;
    asm("fma.rn.f32x2 %0,%1,%2,%3;" : "=l"(d) : "l"(a), "l"(b), "l"(c));
    return d;
}
__device__ __forceinline__ float fast_ex2(float x) {
    float r; asm("ex2.approx.f32 %0,%1;" : "=f"(r) : "f"(x)); return r;
}
__device__ __forceinline__ float fast_rcp(float x) {
    float r; asm("rcp.approx.f32 %0,%1;" : "=f"(r) : "f"(x)); return r;
}
__device__ __forceinline__ float fsigmoid(float x) {
    return fast_rcp(1.0f + fast_ex2(-1.44269504f * x));
}
__device__ __forceinline__ float ftanh(float x) {
    float ax = fabsf(x);
    float t  = fast_ex2(-2.88539008f * ax);          // exp(-2|x|)
    float y  = (1.0f - t) * fast_rcp(1.0f + t);
    return copysignf(y, x);
}

// ---------------------------------------------------------------------------
// GRU scan. Grid 128 x 512 threads. Thread = (row rl=tx>>7, j=lr>>1, half=lr&1).
// Each thread holds 3 gates x 32 K-weights packed as 48 x f32x2 registers.
// Partial dots combined with one shfl_xor(1); gate nonlinearity is intra-pair.
// Hidden state double-buffered in smem -> ONE __syncthreads per timestep.
// gx (= x@W_ih^T + b_ih + b_hh[r,z]) is streamed from g_gx with 1-step prefetch.
// ---------------------------------------------------------------------------
template <int LAYER>
__global__ void __launch_bounds__(512, 1) gru_scan(
    const float* __restrict__ Whh,     // (192,64)
    const float* __restrict__ bhh,     // (192)  (only n-gate part used here)
    float*       __restrict__ outp,    // (B,T,64)
    float*       __restrict__ finalp)  // (B,64)  layer1 only
{
    // [buf][row][half][32 + 4 pad]  -> halves land in different banks
    __shared__ float sh_h[2][4][2][36];

    const int tx   = threadIdx.x;
    const int rl   = tx >> 7;          // row within CTA
    const int lr   = tx & 127;
    const int half = lr & 1;           // k-half: 0 -> k<32, 1 -> k>=32
    const int j    = lr >> 1;          // output index 0..63
    const int kb   = half * 32;

    // 48 packed weight pairs: gates {j, j+64, j+128}, k in [kb, kb+32)
    ull w2[48];
    const ull* __restrict__ Wll = reinterpret_cast<const ull*>(Whh);
#pragma unroll
    for (int g3 = 0; g3 < 3; g3++) {
        const int g = j + g3 * 64;
#pragma unroll
        for (int kk = 0; kk < 16; kk++)
            w2[g3 * 16 + kk] = Wll[(g * 64 + kb) / 2 + kk];
    }
    const float b2 = bhh[j + 128];     // n-gate recurrent bias (must stay inside r*(...))

    for (int i = tx; i < 2 * 4 * 2 * 36; i += 512)
        reinterpret_cast<float*>(sh_h)[i] = 0.0f;
    __syncthreads();

    const int row = blockIdx.x * 4 + rl;
    const float* __restrict__ gxr = &g_gx[(size_t)row * Tsz * Gs];
    float* __restrict__ orow = outp + (size_t)row * Tsz * Hs;

    // software-pipelined gx loads (both lanes load same addrs -> broadcast)
    float xr_c = gxr[j], xz_c = gxr[j + 64], xn_c = gxr[j + 128];
    float hprev = 0.0f;
    int buf = 0;

    for (int t = 0; t < Tsz; t++) {
        // prefetch next step's gx (clamped reload at the last step — harmless)
        const int tn = (t + 1 < Tsz) ? (t + 1) : (Tsz - 1);
        const float* __restrict__ pn_ = gxr + (size_t)tn * Gs;
        const float xr_n = __ldg(pn_ + j);
        const float xz_n = __ldg(pn_ + j + 64);
        const float xn_n = __ldg(pn_ + j + 128);

        // partial recurrent dots over this thread's k-half (f32x2 packed)
        ull a0 = 0ull, a1 = 0ull, a2 = 0ull;
        const ulonglong2* __restrict__ hb =
            reinterpret_cast<const ulonglong2*>(&sh_h[buf][rl][half][0]);
#pragma unroll
        for (int i = 0; i < 8; i++) {
            const ulonglong2 h4 = hb[i];            // LDS.128, bank-clean broadcast
            a0 = ffma2(h4.x, w2[2 * i],          a0);
            a0 = ffma2(h4.y, w2[2 * i + 1],      a0);
            a1 = ffma2(h4.x, w2[16 + 2 * i],     a1);
            a1 = ffma2(h4.y, w2[16 + 2 * i + 1], a1);
            a2 = ffma2(h4.x, w2[32 + 2 * i],     a2);
            a2 = ffma2(h4.y, w2[32 + 2 * i + 1], a2);
        }
        float s0l, s0h, s1l, s1h, s2l, s2h;
        unpack2(a0, s0l, s0h); unpack2(a1, s1l, s1h); unpack2(a2, s2l, s2h);
        float pr = s0l + s0h, pz = s1l + s1h, pn = s2l + s2h;
        pr += __shfl_xor_sync(0xffffffffu, pr, 1);
        pz += __shfl_xor_sync(0xffffffffu, pz, 1);
        pn += __shfl_xor_sync(0xffffffffu, pn, 1);

        if (half == 0) {
            // gx already contains b_ih (+ b_hh for r,z); b_hh[n] applied here
            const float r  = fsigmoid(xr_c + pr);
            const float z  = fsigmoid(xz_c + pz);
            const float nn = ftanh(fmaf(r, pn + b2, xn_c));
            const float hn = fmaf(z, hprev - nn, nn);   // (1-z)*n + z*h
            hprev = hn;
            sh_h[buf ^ 1][rl][j >> 5][j & 31] = hn;
            orow[(size_t)t * Hs + j] = hn;
            if (LAYER == 1 && t == Tsz - 1)
                finalp[row * Hs + j] = hn;
        }
        xr_c = xr_n; xz_c = xz_n; xn_c = xn_n;
        __syncthreads();                                 // one barrier per step
        buf ^= 1;
    }
}

// ---------------------------------------------------------------------------
// gx (layer 0): gx[row,g] = x[row,:3] . W_ih0[g,:3] + b_ih0[g] + (g<128 ? b_hh0[g] : 0)
// grid*block chosen so each thread's g-quad is fixed (444*256 % 48 == 0).
// ---------------------------------------------------------------------------
__global__ void __launch_bounds__(256) gx_gemm3(
    const float* __restrict__ Wih, const float* __restrict__ bih,
    const float* __restrict__ bhh, const float* __restrict__ x)
{
    const size_t nq   = MROWS * 48;                       // float4 quads
    const size_t step = (size_t)gridDim.x * blockDim.x;   // multiple of 48
    size_t q = (size_t)blockIdx.x * blockDim.x + threadIdx.x;
    const int gq = (int)(q % 48) * 4;                     // fixed per thread

    float w[12], bb[4];
#pragma unroll
    for (int c = 0; c < 4; c++) {
        const int g = gq + c;
        w[c * 3 + 0] = Wih[g * 3 + 0];
        w[c * 3 + 1] = Wih[g * 3 + 1];
        w[c * 3 + 2] = Wih[g * 3 + 2];
        bb[c] = bih[g] + (g < 128 ? bhh[g] : 0.0f);
    }
    for (; q < nq; q += step) {
        const size_t row = q / 48;
        const float x0 = x[row * 3], x1 = x[row * 3 + 1], x2 = x[row * 3 + 2];
        float4 o;
        o.x = fmaf(x2, w[2],  fmaf(x1, w[1],  fmaf(x0, w[0], bb[0])));
        o.y = fmaf(x2, w[5],  fmaf(x1, w[4],  fmaf(x0, w[3], bb[1])));
        o.z = fmaf(x2, w[8],  fmaf(x1, w[7],  fmaf(x0, w[6], bb[2])));
        o.w = fmaf(x2, w[11], fmaf(x1, w[10], fmaf(x0, w[9], bb[3])));
        *reinterpret_cast<float4*>(&g_gx[row * Gs + gq]) = o;
    }
}

// ---------------------------------------------------------------------------
// gx (layer 1): gx[row,g] = h1[row,:64] . W_ih1[g,:64] + b_ih1[g] (+b_hh1 r,z)
// f32x2-packed dot, weights in registers, h row broadcast via LDG.128 (L1 hit).
// ---------------------------------------------------------------------------
__global__ void __launch_bounds__(384, 2) gx_gemm64(
    const float* __restrict__ W, const float* __restrict__ bih,
    const float* __restrict__ bhh, const float* __restrict__ hin)
{
    const int tx = threadIdx.x;
    const int g  = tx % Gs;
    const int rg = tx / Gs;           // 0 or 1

    ull w2[32];
    const ull* __restrict__ Wll = reinterpret_cast<const ull*>(W);
#pragma unroll
    for (int i = 0; i < 32; i++) w2[i] = Wll[g * 32 + i];
    const float bi = bih[g] + (g < 128 ? bhh[g] : 0.0f);

    const size_t stride = (size_t)gridDim.x * 2;
    for (size_t row = (size_t)blockIdx.x * 2 + rg; row < MROWS; row += stride) {
        const ulonglong2* __restrict__ hr =
            reinterpret_cast<const ulonglong2*>(&hin[row * Hs]);
        ull a0 = 0ull, a1 = 0ull;
#pragma unroll
        for (int i = 0; i < 16; i++) {
            const ulonglong2 h4 = hr[i];
            a0 = ffma2(h4.x, w2[2 * i],     a0);
            a1 = ffma2(h4.y, w2[2 * i + 1], a1);
        }
        float l0, h0, l1, h1;
        unpack2(a0, l0, h0); unpack2(a1, l1, h1);
        g_gx[row * Gs + g] = bi + ((l0 + h0) + (l1 + h1));
    }
}

// ---------------------------------------------------------------------------
extern "C" void kernel_launch(void* const* d_in, const int* in_sizes, int n_in,
                              void* d_out, int out_size)
{
    (void)in_sizes; (void)n_in; (void)out_size;
    const float* x     = (const float*)d_in[0];
    const float* W_ih0 = (const float*)d_in[1];
    const float* W_hh0 = (const float*)d_in[2];
    const float* b_ih0 = (const float*)d_in[3];
    const float* b_hh0 = (const float*)d_in[4];
    const float* W_ih1 = (const float*)d_in[5];
    const float* W_hh1 = (const float*)d_in[6];
    const float* b_ih1 = (const float*)d_in[7];
    const float* b_hh1 = (const float*)d_in[8];

    float* out    = (float*)d_out;
    float* finalh = out + MROWS * Hs;

    float* d_h1;
    cudaGetSymbolAddress((void**)&d_h1, g_h1);

    gx_gemm3 <<<444, 256>>>(W_ih0, b_ih0, b_hh0, x);
    gru_scan<0><<<128, 512>>>(W_hh0, b_hh0, d_h1, nullptr);
    gx_gemm64<<<592, 384>>>(W_ih1, b_ih1, b_hh1, d_h1);
    gru_scan<1><<<128, 512>>>(W_hh1, b_hh1, out, finalh);
}

// round 3
// speedup vs baseline: 2.3886x; 1.5988x over previous
#include <cuda_runtime.h>
#include <cstddef>

namespace {
constexpr int Bsz = 512, Tsz = 1024, Hs = 64;
}

using ull = unsigned long long;

__device__ __forceinline__ void unpack2(ull v, float& lo, float& hi) {
    asm("mov.b64 {%0,%1},%2;" : "=f"(lo), "=f"(hi) : "l"(v));
}
__device__ __forceinline__ ull ffma2(ull a, ull b, ull c) {
    ull d;
    asm("fma.rn.f32x2 %0,%1,%2,%3;" : "=l"(d) : "l"(a), "l"(b), "l"(c));
    return d;
}
__device__ __forceinline__ float fast_ex2(float x) {
    float r; asm("ex2.approx.f32 %0,%1;" : "=f"(r) : "f"(x)); return r;
}
__device__ __forceinline__ float fast_rcp(float x) {
    float r; asm("rcp.approx.f32 %0,%1;" : "=f"(r) : "f"(x)); return r;
}
__device__ __forceinline__ float fsigmoid(float x) {
    return fast_rcp(1.0f + fast_ex2(-1.44269504f * x));
}
__device__ __forceinline__ float ftanh(float x) {
    float ax = fabsf(x);
    float t  = fast_ex2(-2.88539008f * ax);          // exp(-2|x|)
    float y  = (1.0f - t) * fast_rcp(1.0f + t);
    return copysignf(y, x);
}

// ---------------------------------------------------------------------------
// Fully fused 2-layer GRU. Grid 128 x 384. CTA owns 4 batch rows; layer 1
// trails layer 0 by one timestep (skewed pipeline), so all three GEMVs per
// step run concurrently:
//   m=0 : Whh0 . h1[t-1]          (layer-0 recurrent)
//   m=1 : Wih1 . h1[t-1]          (layer-1 input proj for time t-1)
//   m=2 : Whh1 . h2[t-2]          (layer-1 recurrent)
// Thread = (m = tx>>7, j = (tx&127)>>1, half = tx&1): 3 gates x 32-k-half as
// 48 packed f32x2 weight regs; pair reduced with one shfl_xor.
// Combine: m=0 half0 lanes emit h1[t]; m=2 half0 lanes emit h2[t-1] -> out.
// Two __syncthreads per step, T+1 steps, no global scratch at all.
// ---------------------------------------------------------------------------
__global__ void __launch_bounds__(384, 1) gru_fused(
    const float* __restrict__ x,
    const float* __restrict__ W_ih0, const float* __restrict__ W_hh0,
    const float* __restrict__ b_ih0, const float* __restrict__ b_hh0,
    const float* __restrict__ W_ih1, const float* __restrict__ W_hh1,
    const float* __restrict__ b_ih1, const float* __restrict__ b_hh1,
    float* __restrict__ outp,        // (B,T,64)
    float* __restrict__ finalp)      // (B,64)
{
    // [buf][row][half][32+4 pad] -> halves in disjoint banks, 16B aligned
    __shared__ float sh_h1[2][4][2][36];
    __shared__ float sh_h2[2][4][2][36];
    __shared__ float sh_xa[4][3][64];    // layer-1 gx gates (from m=1)
    __shared__ float sh_x [4][3];        // x[t] per row

    const int tx   = threadIdx.x;
    const int m    = tx >> 7;            // matrix slot 0..2
    const int lr   = tx & 127;
    const int half = lr & 1;
    const int j    = lr >> 1;            // output unit 0..63
    const int kb   = half * 32;

    // --- weights: 3 gate-rows (j, j+64, j+128) of this thread's matrix ---
    const float* __restrict__ Wm = (m == 0) ? W_hh0 : (m == 1) ? W_ih1 : W_hh1;
    ull w2[48];
    const ull* __restrict__ Wll = reinterpret_cast<const ull*>(Wm);
#pragma unroll
    for (int g3 = 0; g3 < 3; g3++) {
        const int g = j + g3 * 64;
#pragma unroll
        for (int kk = 0; kk < 16; kk++)
            w2[g3 * 16 + kk] = Wll[(g * 64 + kb) / 2 + kk];
    }

    // --- per-m biases / layer-0 input weights ---
    float wi0[9];
    float ba = 0.f, bb_ = 0.f, bc = 0.f, bd = 0.f;
    if (m == 0) {
#pragma unroll
        for (int g3 = 0; g3 < 3; g3++)
#pragma unroll
            for (int c = 0; c < 3; c++)
                wi0[g3 * 3 + c] = W_ih0[(j + g3 * 64) * 3 + c];
        ba  = b_ih0[j]       + b_hh0[j];        // r
        bb_ = b_ih0[j + 64]  + b_hh0[j + 64];   // z
        bc  = b_ih0[j + 128];                    // n (input side)
        bd  = b_hh0[j + 128];                    // n (recurrent side, inside r*)
    } else if (m == 1) {
        ba  = b_ih1[j]       + b_hh1[j];
        bb_ = b_ih1[j + 64]  + b_hh1[j + 64];
        bc  = b_ih1[j + 128];
#pragma unroll
        for (int c = 0; c < 9; c++) wi0[c] = 0.f;
    } else {
        bd  = b_hh1[j + 128];
#pragma unroll
        for (int c = 0; c < 9; c++) wi0[c] = 0.f;
    }

    // zero both hidden-state buffers (h1[-1]=0, h2[-1]=0 across both bufs)
    for (int i = tx; i < 2 * 4 * 2 * 36; i += 384) {
        reinterpret_cast<float*>(sh_h1)[i] = 0.f;
        reinterpret_cast<float*>(sh_h2)[i] = 0.f;
    }
    __syncthreads();

    const int row4 = blockIdx.x * 4;
    float pr0[4], pz0[4], pn0[4];      // reduced dot partials (m=0 / m=2 lanes)
    int buf = 0;

    for (int t = 0; t <= Tsz; t++) {
        // ---------------- phase A: three GEMVs, 4 rows each ----------------
        const float* __restrict__ shsrc =
            (m == 2) ? &sh_h2[buf][0][half][0] : &sh_h1[buf][0][half][0];
#pragma unroll
        for (int r = 0; r < 4; r++) {
            const ulonglong2* __restrict__ hb =
                reinterpret_cast<const ulonglong2*>(shsrc + r * 2 * 36);
            ull a0 = 0ull, a1 = 0ull, a2 = 0ull;
#pragma unroll
            for (int i = 0; i < 8; i++) {
                const ulonglong2 h4 = hb[i];               // LDS.128
                a0 = ffma2(h4.x, w2[2 * i],          a0);
                a0 = ffma2(h4.y, w2[2 * i + 1],      a0);
                a1 = ffma2(h4.x, w2[16 + 2 * i],     a1);
                a1 = ffma2(h4.y, w2[16 + 2 * i + 1], a1);
                a2 = ffma2(h4.x, w2[32 + 2 * i],     a2);
                a2 = ffma2(h4.y, w2[32 + 2 * i + 1], a2);
            }
            float l, h;
            unpack2(a0, l, h); float pr = l + h;
            unpack2(a1, l, h); float pz = l + h;
            unpack2(a2, l, h); float pn = l + h;
            pr += __shfl_xor_sync(0xffffffffu, pr, 1);
            pz += __shfl_xor_sync(0xffffffffu, pz, 1);
            pn += __shfl_xor_sync(0xffffffffu, pn, 1);
            if (m == 1) {
                if (half == 0) {                 // post gx1[t-1] gates (+bias)
                    sh_xa[r][0][j] = pr + ba;
                    sh_xa[r][1][j] = pz + bb_;
                    sh_xa[r][2][j] = pn + bc;
                }
            } else {
                pr0[r] = pr; pz0[r] = pz; pn0[r] = pn;
            }
        }
        // stage x[t] (12 designated threads)
        if (m == 1 && half == 1 && j < 3 && t < Tsz) {
#pragma unroll
            for (int r = 0; r < 4; r++)
                sh_x[r][j] = __ldg(&x[((size_t)(row4 + r) * Tsz + t) * 3 + j]);
        }
        __syncthreads();

        // ---------------- phase B: gate combines ----------------
        if (half == 0 && m == 0 && t < Tsz) {      // h1[t]
#pragma unroll
            for (int r = 0; r < 4; r++) {
                const float x0 = sh_x[r][0], x1 = sh_x[r][1], x2 = sh_x[r][2];
                const float xar = fmaf(x2, wi0[2], fmaf(x1, wi0[1], fmaf(x0, wi0[0], ba)));
                const float xaz = fmaf(x2, wi0[5], fmaf(x1, wi0[4], fmaf(x0, wi0[3], bb_)));
                const float xan = fmaf(x2, wi0[8], fmaf(x1, wi0[7], fmaf(x0, wi0[6], bc)));
                const float rr = fsigmoid(xar + pr0[r]);
                const float zz = fsigmoid(xaz + pz0[r]);
                const float nn = ftanh(fmaf(rr, pn0[r] + bd, xan));
                const float hp = sh_h1[buf][r][j >> 5][j & 31];
                const float hn = fmaf(zz, hp - nn, nn);
                sh_h1[buf ^ 1][r][j >> 5][j & 31] = hn;
            }
        }
        if (half == 0 && m == 2 && t > 0) {        // h2[t-1] -> output
#pragma unroll
            for (int r = 0; r < 4; r++) {
                const float xar = sh_xa[r][0][j];
                const float xaz = sh_xa[r][1][j];
                const float xan = sh_xa[r][2][j];
                const float rr = fsigmoid(xar + pr0[r]);
                const float zz = fsigmoid(xaz + pz0[r]);
                const float nn = ftanh(fmaf(rr, pn0[r] + bd, xan));
                const float hp = sh_h2[buf][r][j >> 5][j & 31];
                const float hn = fmaf(zz, hp - nn, nn);
                sh_h2[buf ^ 1][r][j >> 5][j & 31] = hn;
                outp[((size_t)(row4 + r) * Tsz + (t - 1)) * Hs + j] = hn;
                if (t == Tsz)
                    finalp[(row4 + r) * Hs + j] = hn;
            }
        }
        __syncthreads();
        buf ^= 1;
    }
}

// ---------------------------------------------------------------------------
extern "C" void kernel_launch(void* const* d_in, const int* in_sizes, int n_in,
                              void* d_out, int out_size)
{
    (void)in_sizes; (void)n_in; (void)out_size;
    const float* x     = (const float*)d_in[0];
    const float* W_ih0 = (const float*)d_in[1];
    const float* W_hh0 = (const float*)d_in[2];
    const float* b_ih0 = (const float*)d_in[3];
    const float* b_hh0 = (const float*)d_in[4];
    const float* W_ih1 = (const float*)d_in[5];
    const float* W_hh1 = (const float*)d_in[6];
    const float* b_ih1 = (const float*)d_in[7];
    const float* b_hh1 = (const float*)d_in[8];

    float* out    = (float*)d_out;
    float* finalh = out + (size_t)Bsz * Tsz * Hs;

    gru_fused<<<128, 384>>>(x, W_ih0, W_hh0, b_ih0, b_hh0,
                            W_ih1, W_hh1, b_ih1, b_hh1, out, finalh);
}